// round 9
// baseline (speedup 1.0000x reference)
#include <cuda_runtime.h>
#include <cuda_fp16.h>

// ---------------------------------------------------------------------------
// N=512, MAX_DIST=16, H=32, N_SPATIAL=64, BOND_TYPES=32.
// edge_sum[i,j,k] = sum_d T[d][edge_input[i,j,d]][k],  T[d] = edge_table @ W[d]
// Single persistent kernel, grid = 888 = 6/SM x 148 (co-residency guaranteed
// by 36.9KB smem -> exactly 6 blocks/SM; regs capped by __launch_bounds__).
//   Phase 1: blocks 0..15 compute T[d] (smem-staged GEMM, fp32); ALL blocks
//            pack per-pair indices (byte offsets, x4) into uint4 + {sp,1/sp}.
//   Global sense-reversing barrier (self-resetting across graph replays).
//   Phase 2: conflict-free LDS.32 gather (bank = e), fp16 group trees,
//            2 pairs/thread -> all stores STG.64; dynamic work stealing.
// R8 bugfix: shS offset was in "words" while sh is float* (2*T2_ELEMS floats
// = 64KB, past the 36.9KB allocation -> illegal access). Now sh + T2_ELEMS.
// ---------------------------------------------------------------------------

#define NN        512
#define PAIRS     (NN * NN)          // 262144
#define MAXD      16
#define H         32
#define NSPAT     64
#define T2_ELEMS  (MAXD * 16 * 32)   // 8192 half2 = 32KB (also 8192 floats)
#define SHS_U2    512                // 8 k2p * 64 sp uint2 = 4KB
#define SMEM_BYTES (T2_ELEMS * 4 + SHS_U2 * 8)   // 36864
#define GRID      888               // 6 blocks/SM * 148 SMs (single wave)
#define N_TASKS   4096              // 512 tiles(512 pairs) * 8 k2p
#define TOT_THREADS (GRID * 256)    // 227328

__device__ __half2   g_T2[T2_ELEMS];   // [d][k2][e]
__device__ uint4     g_packed[PAIRS];  // 16 indices, pre-scaled x4, one byte each
__device__ int2      g_aux[PAIRS];     // {sp, bits(1/max(sp,1))}
__device__ unsigned  g_task_counter;
__device__ unsigned  g_bar_count;
__device__ unsigned  g_bar_sense;

static __device__ __forceinline__ float2 h2f(__half2 h) {
    return __half22float2(h);
}
static __device__ __forceinline__ unsigned h2bits(__half2 h) {
    return *reinterpret_cast<unsigned*>(&h);
}

__global__ __launch_bounds__(256, 6)
void bond_encoding_kernel(const int* __restrict__ spatial_pos,
                          const int* __restrict__ edge_input,
                          const float* __restrict__ spd_table,
                          const float* __restrict__ edge_table,
                          const float* __restrict__ W,
                          float* __restrict__ out) {
    extern __shared__ float sh[];
    __shared__ int mail[2];
    const int t   = threadIdx.x;
    const int bid = blockIdx.x;

    // ---------------- Phase 1 ----------------
    if (bid < MAXD) {
        // Compute T[d] = edge_table @ W[d], stored half2 over k, [d][k2][e].
        float* shE = sh;            // [h][e]
        float* shW = sh + H * H;    // [h][k]
        int d = bid;
        for (int i = t; i < H * H; i += 256) {
            int e = i >> 5, h = i & 31;
            shE[h * H + e] = edge_table[i];
            shW[i] = W[d * (H * H) + i];
        }
        __syncthreads();
        int e = t & 31;
#pragma unroll
        for (int rep = 0; rep < 2; ++rep) {
            int k2 = (t >> 5) + 8 * rep;
            float s0 = 0.0f, s1 = 0.0f;
#pragma unroll
            for (int h = 0; h < H; ++h) {
                float ev = shE[h * H + e];          // bank = e
                s0 += ev * shW[h * H + 2 * k2];     // broadcast (k2 warp-uniform)
                s1 += ev * shW[h * H + 2 * k2 + 1];
            }
            g_T2[d * 512 + k2 * 32 + e] = __floats2half2_rn(s0, s1);
        }
        __syncthreads();   // shE/shW reuse below (phase-2 staging) is safe
    }
    if (bid == 0 && t == 0) g_task_counter = 0u;

    // All blocks: pack indices + aux (<= 2 pairs per thread).
    {
        int gtid = bid * 256 + t;
#pragma unroll
        for (int rep = 0; rep < 2; ++rep) {
            int pair = gtid + rep * TOT_THREADS;
            if (pair < PAIRS) {
                const int4* ep = (const int4*)edge_input + pair * 4;
                int4 a = ep[0], b = ep[1], c = ep[2], e4 = ep[3];
                uint4 r;
                r.x = ((unsigned)a.x  << 2) | ((unsigned)a.y  << 10) | ((unsigned)a.z  << 18) | ((unsigned)a.w  << 26);
                r.y = ((unsigned)b.x  << 2) | ((unsigned)b.y  << 10) | ((unsigned)b.z  << 18) | ((unsigned)b.w  << 26);
                r.z = ((unsigned)c.x  << 2) | ((unsigned)c.y  << 10) | ((unsigned)c.z  << 18) | ((unsigned)c.w  << 26);
                r.w = ((unsigned)e4.x << 2) | ((unsigned)e4.y << 10) | ((unsigned)e4.z << 18) | ((unsigned)e4.w << 26);
                g_packed[pair] = r;
                int sp = spatial_pos[pair];
                float rden = (sp == 0) ? 1.0f : (1.0f / (float)sp);
                g_aux[pair] = make_int2(sp, __float_as_int(rden));
            }
        }
    }

    // ---------------- Global barrier (sense-reversing, replay-safe) --------
    __threadfence();
    __syncthreads();
    if (t == 0) {
        unsigned s0 = *(volatile unsigned*)&g_bar_sense;
        unsigned old = atomicAdd(&g_bar_count, 1u);
        if (old == GRID - 1) {
            g_bar_count = 0u;
            __threadfence();
            *(volatile unsigned*)&g_bar_sense = s0 + 1u;
        } else {
            while (*(volatile unsigned*)&g_bar_sense == s0) __nanosleep(128);
        }
        __threadfence();
        mail[0] = (int)atomicAdd(&g_task_counter, 1u);
    }
    __syncthreads();

    // ---------------- Phase 2: stage smem ----------------
    __half2* shT = (__half2*)sh;              // [d][k2][e], 32KB = 8192 floats
    uint2*   shS = (uint2*)(sh + T2_ELEMS);   // [k2p][sp], 4KB  (FIX: float units)
    {
        const float4* src = (const float4*)g_T2;
        float4* dst = (float4*)shT;
#pragma unroll
        for (int i = t; i < T2_ELEMS / 4; i += 256)
            dst[i] = src[i];
    }
    for (int i = t; i < SHS_U2; i += 256) {
        int k2p = i >> 6;
        int sp  = i & 63;
        __half2 lo = __floats2half2_rn(spd_table[sp * H + 4 * k2p],
                                       spd_table[sp * H + 4 * k2p + 1]);
        __half2 hi = __floats2half2_rn(spd_table[sp * H + 4 * k2p + 2],
                                       spd_table[sp * H + 4 * k2p + 3]);
        shS[i] = make_uint2(h2bits(lo), h2bits(hi));
    }
    __syncthreads();

    // ---------------- Phase 2: main loop (work stealing) ----------------
    int task = mail[0];
    int slot = 1;
    while (task < N_TASKS) {
        if (t == 0) mail[slot] = (int)atomicAdd(&g_task_counter, 1u);

        int tile  = task >> 3;
        int k2p   = task & 7;                    // 4 heads: k = 4*k2p..4*k2p+3
        int pairA = tile * 512 + t * 2;

        uint4 pkA = g_packed[pairA];
        uint4 pkB = g_packed[pairA + 1];
        int4  aux = *((const int4*)g_aux + (pairA >> 1));  // {spA,rdA,spB,rdB}

        // byte base of (d=0, k2=2*k2p, e=0) in shT
        const char* baseT = (const char*)shT + (2 * k2p) * 128;

        float eA[4], eB[4];
#pragma unroll
        for (int pp = 0; pp < 2; ++pp) {
            uint4 pk4 = pp ? pkB : pkA;
            float rden = __int_as_float(pp ? aux.w : aux.y);
            unsigned pk[4] = { pk4.x, pk4.y, pk4.z, pk4.w };
            float a0 = 0.0f, a1 = 0.0f, a2 = 0.0f, a3 = 0.0f;
#pragma unroll
            for (int g = 0; g < 4; ++g) {        // d = 4g..4g+3
                const char* bg = baseT + g * 8192;   // 4 d * 2048B
                unsigned o0 =  pk[g]        & 0xFCu;
                unsigned o1 = (pk[g] >> 8)  & 0xFCu;
                unsigned o2 = (pk[g] >> 16) & 0xFCu;
                unsigned o3 = (pk[g] >> 24);
                const __half2* p0 = (const __half2*)(bg          + o0);
                const __half2* p1 = (const __half2*)(bg + 2048   + o1);
                const __half2* p2 = (const __half2*)(bg + 4096   + o2);
                const __half2* p3 = (const __half2*)(bg + 6144   + o3);
                // slot j=0: k2 = 2*k2p ; slot j=1: k2 = 2*k2p+1 (+32 half2)
                __half2 t0 = __hadd2(__hadd2(p0[0],  p1[0]),  __hadd2(p2[0],  p3[0]));
                __half2 t1 = __hadd2(__hadd2(p0[32], p1[32]), __hadd2(p2[32], p3[32]));
                float2 f0 = h2f(t0), f1 = h2f(t1);
                a0 = fmaf(f0.x, rden, a0);
                a1 = fmaf(f0.y, rden, a1);
                a2 = fmaf(f1.x, rden, a2);
                a3 = fmaf(f1.y, rden, a3);
            }
            if (pp) { eB[0] = a0; eB[1] = a1; eB[2] = a2; eB[3] = a3; }
            else    { eA[0] = a0; eA[1] = a1; eA[2] = a2; eA[3] = a3; }
        }

        int k0 = 4 * k2p;
        float* oe = out + (H + k0) * PAIRS + pairA;
        __stcs((float2*)(oe + 0 * PAIRS), make_float2(eA[0], eB[0]));
        __stcs((float2*)(oe + 1 * PAIRS), make_float2(eA[1], eB[1]));
        __stcs((float2*)(oe + 2 * PAIRS), make_float2(eA[2], eB[2]));
        __stcs((float2*)(oe + 3 * PAIRS), make_float2(eA[3], eB[3]));

        uint2 sA = shS[k2p * NSPAT + aux.x];
        uint2 sB = shS[k2p * NSPAT + aux.z];
        float2 a0 = h2f(*(__half2*)&sA.x), a1 = h2f(*(__half2*)&sA.y);
        float2 b0 = h2f(*(__half2*)&sB.x), b1 = h2f(*(__half2*)&sB.y);
        float* os = out + k0 * PAIRS + pairA;
        __stcs((float2*)(os + 0 * PAIRS), make_float2(a0.x, b0.x));
        __stcs((float2*)(os + 1 * PAIRS), make_float2(a0.y, b0.y));
        __stcs((float2*)(os + 2 * PAIRS), make_float2(a1.x, b1.x));
        __stcs((float2*)(os + 3 * PAIRS), make_float2(a1.y, b1.y));

        __syncthreads();       // publishes mail[slot]
        task = mail[slot];
        slot ^= 1;
    }
}

extern "C" void kernel_launch(void* const* d_in, const int* in_sizes, int n_in,
                              void* d_out, int out_size) {
    const int*   spatial_pos = nullptr;
    const int*   edge_input  = nullptr;
    const float* spd_table   = nullptr;
    const float* edge_table  = nullptr;
    const float* W           = nullptr;
    for (int i = 0; i < n_in; ++i) {
        switch (in_sizes[i]) {
            case PAIRS:          spatial_pos = (const int*)d_in[i];   break;
            case PAIRS * MAXD:   edge_input  = (const int*)d_in[i];   break;
            case NSPAT * H:      spd_table   = (const float*)d_in[i]; break;
            case H * H:          edge_table  = (const float*)d_in[i]; break;
            case NSPAT * H * H:  W           = (const float*)d_in[i]; break;
            default: break;
        }
    }

    cudaFuncSetAttribute(bond_encoding_kernel,
                         cudaFuncAttributeMaxDynamicSharedMemorySize, SMEM_BYTES);
    bond_encoding_kernel<<<GRID, 256, SMEM_BYTES>>>(
        spatial_pos, edge_input, spd_table, edge_table, W, (float*)d_out);
}

// round 10
// speedup vs baseline: 1.0786x; 1.0786x over previous
#include <cuda_runtime.h>
#include <cuda_fp16.h>

// ---------------------------------------------------------------------------
// N=512, MAX_DIST=16, H=32, N_SPATIAL=64, BOND_TYPES=32.
// edge_sum[i,j,k] = sum_d T[d][edge_input[i,j,d]][k],  T[d] = edge_table @ W[d]
// Persistent fused kernel (grid=888 = 6/SM x 148, co-residency pinned by
// 36.9KB smem). Phase 1: blocks 0..15 compute T[d]; ALL blocks pack indices
// (x4 byte offsets) + {sp,1/sp}. Global sense-reversing barrier. Phase 2 =
// ROUND-6 loop verbatim (the validated optimum): 1 pair/thread, 256-pair tile
// x k-quarter (8 heads), conflict-free LDS.32 gather (bank = e), fp16
// group-of-4 trees + fp32 FFMA, STG.32 streaming stores, work stealing.
// (R9 lesson: 4-head/2-pair tasks regress ~8us; do not perturb the loop.)
// ---------------------------------------------------------------------------

#define NN        512
#define PAIRS     (NN * NN)          // 262144
#define MAXD      16
#define H         32
#define NSPAT     64
#define T2_ELEMS  (MAXD * 16 * 32)   // 8192 half2 = 32KB (= 8192 floats)
#define SHS_ELEMS (16 * NSPAT)       // 1024 half2 = 4KB
#define SMEM_BYTES (T2_ELEMS * 4 + SHS_ELEMS * 4)   // 36864
#define GRID      888               // 6 blocks/SM * 148 SMs (single wave)
#define N_TASKS   4096              // 1024 tiles(256 pairs) * 4 k-quarters
#define TOT_THREADS (GRID * 256)    // 227328

__device__ __half2   g_T2[T2_ELEMS];   // [d][k2][e]
__device__ uint4     g_packed[PAIRS];  // 16 indices, pre-scaled x4, one byte each
__device__ int2      g_aux[PAIRS];     // {sp, bits(1/max(sp,1))}
__device__ unsigned  g_task_counter;
__device__ unsigned  g_bar_count;
__device__ unsigned  g_bar_sense;

__global__ __launch_bounds__(256, 6)
void bond_encoding_kernel(const int* __restrict__ spatial_pos,
                          const int* __restrict__ edge_input,
                          const float* __restrict__ spd_table,
                          const float* __restrict__ edge_table,
                          const float* __restrict__ W,
                          float* __restrict__ out) {
    extern __shared__ float sh[];
    __shared__ int mail[2];
    const int t   = threadIdx.x;
    const int bid = blockIdx.x;

    // ---------------- Phase 1 ----------------
    if (bid < MAXD) {
        float* shE = sh;            // [h][e]
        float* shW = sh + H * H;    // [h][k]
        int d = bid;
        for (int i = t; i < H * H; i += 256) {
            int e = i >> 5, h = i & 31;
            shE[h * H + e] = edge_table[i];
            shW[i] = W[d * (H * H) + i];
        }
        __syncthreads();
        int e = t & 31;
#pragma unroll
        for (int rep = 0; rep < 2; ++rep) {
            int k2 = (t >> 5) + 8 * rep;
            float s0 = 0.0f, s1 = 0.0f;
#pragma unroll
            for (int h = 0; h < H; ++h) {
                float ev = shE[h * H + e];          // bank = e
                s0 += ev * shW[h * H + 2 * k2];     // broadcast (k2 warp-uniform)
                s1 += ev * shW[h * H + 2 * k2 + 1];
            }
            g_T2[d * 512 + k2 * 32 + e] = __floats2half2_rn(s0, s1);
        }
        __syncthreads();
    }
    if (bid == 0 && t == 0) g_task_counter = 0u;

    // All blocks: pack indices + aux (<= 2 pairs per thread).
    {
        int gtid = bid * 256 + t;
#pragma unroll
        for (int rep = 0; rep < 2; ++rep) {
            int pair = gtid + rep * TOT_THREADS;
            if (pair < PAIRS) {
                const int4* ep = (const int4*)edge_input + pair * 4;
                int4 a = ep[0], b = ep[1], c = ep[2], e4 = ep[3];
                uint4 r;
                r.x = ((unsigned)a.x  << 2) | ((unsigned)a.y  << 10) | ((unsigned)a.z  << 18) | ((unsigned)a.w  << 26);
                r.y = ((unsigned)b.x  << 2) | ((unsigned)b.y  << 10) | ((unsigned)b.z  << 18) | ((unsigned)b.w  << 26);
                r.z = ((unsigned)c.x  << 2) | ((unsigned)c.y  << 10) | ((unsigned)c.z  << 18) | ((unsigned)c.w  << 26);
                r.w = ((unsigned)e4.x << 2) | ((unsigned)e4.y << 10) | ((unsigned)e4.z << 18) | ((unsigned)e4.w << 26);
                g_packed[pair] = r;
                int sp = spatial_pos[pair];
                float rden = (sp == 0) ? 1.0f : (1.0f / (float)sp);
                g_aux[pair] = make_int2(sp, __float_as_int(rden));
            }
        }
    }

    // ---------------- Global barrier (sense-reversing, replay-safe) --------
    __threadfence();
    __syncthreads();
    if (t == 0) {
        unsigned s0 = *(volatile unsigned*)&g_bar_sense;
        unsigned old = atomicAdd(&g_bar_count, 1u);
        if (old == GRID - 1) {
            g_bar_count = 0u;
            __threadfence();
            *(volatile unsigned*)&g_bar_sense = s0 + 1u;
        } else {
            while (*(volatile unsigned*)&g_bar_sense == s0) __nanosleep(128);
        }
        __threadfence();
        mail[0] = (int)atomicAdd(&g_task_counter, 1u);
    }
    __syncthreads();

    // ---------------- Phase 2: stage smem ----------------
    __half2* shT = (__half2*)sh;                // [d][k2][e], 32KB
    __half2* shS = (__half2*)sh + T2_ELEMS;     // [k2][sp],   4KB
    {
        const float4* src = (const float4*)g_T2;
        float4* dst = (float4*)shT;
#pragma unroll
        for (int i = t; i < T2_ELEMS / 4; i += 256)
            dst[i] = src[i];
    }
    for (int i = t; i < SHS_ELEMS; i += 256) {
        int k2 = i >> 6;
        int sp = i & 63;
        shS[i] = __floats2half2_rn(spd_table[sp * H + 2 * k2],
                                   spd_table[sp * H + 2 * k2 + 1]);
    }
    __syncthreads();

    // ---------------- Phase 2: main loop (round-6 verbatim) ----------------
    int task = mail[0];
    int slot = 1;
    while (task < N_TASKS) {
        if (t == 0) mail[slot] = (int)atomicAdd(&g_task_counter, 1u);

        int tile = task >> 2;
        int kq   = task & 3;                  // k-quarter: 8 heads
        int pair = tile * 256 + t;

        uint4 pk4 = g_packed[pair];           // one LDG.128: all 16 indices *4
        unsigned pk[4] = { pk4.x, pk4.y, pk4.z, pk4.w };
        int2 aux = g_aux[pair];
        float rden = __int_as_float(aux.y);

        float acc[8];
#pragma unroll
        for (int j = 0; j < 8; ++j) acc[j] = 0.0f;

#pragma unroll
        for (int g = 0; g < 4; ++g) {         // d-group of 4: d = 4g..4g+3
            const char* base = (const char*)(shT + ((4 * g) * 16 + kq * 4) * 32);
            unsigned o0 =  pk[g]        & 0xFCu;
            unsigned o1 = (pk[g] >> 8)  & 0xFCu;
            unsigned o2 = (pk[g] >> 16) & 0xFCu;
            unsigned o3 = (pk[g] >> 24);
            const __half2* p0 = (const __half2*)(base          + o0);
            const __half2* p1 = (const __half2*)(base + 2048   + o1);
            const __half2* p2 = (const __half2*)(base + 4096   + o2);
            const __half2* p3 = (const __half2*)(base + 6144   + o3);
#pragma unroll
            for (int j = 0; j < 4; ++j) {     // 4 k2 slots in this quarter
                __half2 tt = __hadd2(__hadd2(p0[j * 32], p1[j * 32]),
                                     __hadd2(p2[j * 32], p3[j * 32]));
                float2 f = __half22float2(tt);
                acc[2 * j]     = fmaf(f.x, rden, acc[2 * j]);
                acc[2 * j + 1] = fmaf(f.y, rden, acc[2 * j + 1]);
            }
        }

        int k0 = kq * 8;
#pragma unroll
        for (int j = 0; j < 4; ++j) {
            float2 sf = __half22float2(shS[(kq * 4 + j) * NSPAT + aux.x]);
            int k = k0 + 2 * j;
            __stcs(out + k * PAIRS + pair,           sf.x);
            __stcs(out + (k + 1) * PAIRS + pair,     sf.y);
            __stcs(out + (H + k) * PAIRS + pair,     acc[2 * j]);
            __stcs(out + (H + k + 1) * PAIRS + pair, acc[2 * j + 1]);
        }

        __syncthreads();       // publishes mail[slot]
        task = mail[slot];
        slot ^= 1;
    }
}

extern "C" void kernel_launch(void* const* d_in, const int* in_sizes, int n_in,
                              void* d_out, int out_size) {
    const int*   spatial_pos = nullptr;
    const int*   edge_input  = nullptr;
    const float* spd_table   = nullptr;
    const float* edge_table  = nullptr;
    const float* W           = nullptr;
    for (int i = 0; i < n_in; ++i) {
        switch (in_sizes[i]) {
            case PAIRS:          spatial_pos = (const int*)d_in[i];   break;
            case PAIRS * MAXD:   edge_input  = (const int*)d_in[i];   break;
            case NSPAT * H:      spd_table   = (const float*)d_in[i]; break;
            case H * H:          edge_table  = (const float*)d_in[i]; break;
            case NSPAT * H * H:  W           = (const float*)d_in[i]; break;
            default: break;
        }
    }

    cudaFuncSetAttribute(bond_encoding_kernel,
                         cudaFuncAttributeMaxDynamicSharedMemorySize, SMEM_BYTES);
    bond_encoding_kernel<<<GRID, 256, SMEM_BYTES>>>(
        spatial_pos, edge_input, spd_table, edge_table, W, (float*)d_out);
}

// round 11
// speedup vs baseline: 1.2206x; 1.1317x over previous
#include <cuda_runtime.h>
#include <cuda_fp16.h>

// ---------------------------------------------------------------------------
// N=512, MAX_DIST=16, H=32, N_SPATIAL=64, BOND_TYPES=32.
// edge_sum[i,j,k] = sum_d T[d][edge_input[i,j,d]][k],  T[d] = edge_table @ W[d]
// Round-11 split: prep kernel does T-precompute (blocks 0..15) AND the entire
// phi_spd output (pure spd_table gather -> 32MB, L2-resident) AND index/rden
// packing. Main kernel = round-6 gather loop minus phi_spd work: per task-warp
// LSU ops drop 38 -> 26 (the measured binding pipe). Plain STG (no __stcs):
// the 90MB working set is L2-resident, streaming hints only add DRAM traffic.
// ---------------------------------------------------------------------------

#define NN        512
#define PAIRS     (NN * NN)          // 262144
#define MAXD      16
#define H         32
#define NSPAT     64
#define T2_ELEMS  (MAXD * 16 * 32)   // 8192 half2 = 32KB
#define SMEM_BYTES (T2_ELEMS * 4)    // 32768 (main kernel: shT only)
#define GRID      888               // 6 blocks/SM * 148 SMs
#define N_TASKS   4096              // 1024 tiles(256 pairs) * 4 k-quarters

__device__ __half2   g_T2[T2_ELEMS];   // [d][k2][e]
__device__ uint4     g_packed[PAIRS];  // 16 indices, pre-scaled x4, one byte each
__device__ float     g_rden[PAIRS];    // 1/max(sp,1)
__device__ unsigned  g_task_counter;

// Blocks 0..15: T[d]. Blocks 16..271: pack + rden + phi_spd (2 pairs/thread).
__global__ __launch_bounds__(512)
void prep_kernel(const float* __restrict__ edge_table,
                 const float* __restrict__ W,
                 const int* __restrict__ edge_input,
                 const int* __restrict__ spatial_pos,
                 const float* __restrict__ spd_table,
                 float* __restrict__ out) {
    __shared__ float shBuf[2048];   // 8KB: T blocks: shE+shW ; pack: spd transposed
    int t = threadIdx.x;

    if (blockIdx.x < MAXD) {
        float* shE = shBuf;            // [h][e]
        float* shW = shBuf + H * H;    // [h][k]
        int d = blockIdx.x;
        for (int i = t; i < H * H; i += 512) {
            int e = i >> 5, h = i & 31;
            shE[h * H + e] = edge_table[i];
            shW[i] = W[d * (H * H) + i];
        }
        __syncthreads();
        int e  = t & 31;
        int k2 = t >> 5;
        float s0 = 0.0f, s1 = 0.0f;
#pragma unroll
        for (int h = 0; h < H; ++h) {
            float ev = shE[h * H + e];          // bank = e, conflict-free
            s0 += ev * shW[h * H + 2 * k2];     // broadcast (k2 warp-uniform)
            s1 += ev * shW[h * H + 2 * k2 + 1];
        }
        g_T2[d * 512 + k2 * 32 + e] = __floats2half2_rn(s0, s1);
        return;
    }

    if (blockIdx.x == MAXD && t == 0) g_task_counter = 0u;

    // Stage spd_table transposed: shSp[k*64 + sp] (write banks conflict-free)
    float* shSp = shBuf;
    for (int i = t; i < NSPAT * H; i += 512) {
        int k  = i >> 6;
        int sp = i & 63;
        shSp[k * NSPAT + sp] = spd_table[sp * H + k];
    }
    __syncthreads();

    int pA = ((blockIdx.x - MAXD) * 512 + t) * 2;   // 256 blocks cover PAIRS
    int pB = pA + 1;

    // Pack indices for both pairs (byte offsets, x4)
#pragma unroll
    for (int pp = 0; pp < 2; ++pp) {
        int pair = pA + pp;
        const int4* ep = (const int4*)edge_input + pair * 4;
        int4 a = ep[0], b = ep[1], c = ep[2], e4 = ep[3];
        uint4 r;
        r.x = ((unsigned)a.x  << 2) | ((unsigned)a.y  << 10) | ((unsigned)a.z  << 18) | ((unsigned)a.w  << 26);
        r.y = ((unsigned)b.x  << 2) | ((unsigned)b.y  << 10) | ((unsigned)b.z  << 18) | ((unsigned)b.w  << 26);
        r.z = ((unsigned)c.x  << 2) | ((unsigned)c.y  << 10) | ((unsigned)c.z  << 18) | ((unsigned)c.w  << 26);
        r.w = ((unsigned)e4.x << 2) | ((unsigned)e4.y << 10) | ((unsigned)e4.z << 18) | ((unsigned)e4.w << 26);
        g_packed[pair] = r;
    }

    // sp + rden for both pairs (pA even -> int2/float2 aligned)
    int2 s = ((const int2*)spatial_pos)[pA >> 1];
    float rA = (s.x == 0) ? 1.0f : (1.0f / (float)s.x);
    float rB = (s.y == 0) ? 1.0f : (1.0f / (float)s.y);
    *(float2*)(g_rden + pA) = make_float2(rA, rB);

    // phi_spd: out[k*PAIRS + pair] = spd_table[sp][k], STG.64 over pair-pairs
#pragma unroll
    for (int k = 0; k < H; ++k) {
        float va = shSp[k * NSPAT + s.x];
        float vb = shSp[k * NSPAT + s.y];
        *(float2*)(out + k * PAIRS + pA) = make_float2(va, vb);
    }
}

__global__ __launch_bounds__(256, 6)
void bond_encoding_kernel(float* __restrict__ out) {
    extern __shared__ float sh[];
    __half2* shT = (__half2*)sh;              // [d][k2][e], 32KB
    __shared__ int mail[2];
    const int t = threadIdx.x;

    {
        const float4* src = (const float4*)g_T2;
        float4* dst = (float4*)sh;
#pragma unroll
        for (int i = t; i < T2_ELEMS / 4; i += 256)
            dst[i] = src[i];
    }
    if (t == 0) mail[0] = (int)atomicAdd(&g_task_counter, 1u);
    __syncthreads();

    int task = mail[0];
    int slot = 1;
    while (task < N_TASKS) {
        if (t == 0) mail[slot] = (int)atomicAdd(&g_task_counter, 1u);

        int tile = task >> 2;
        int kq   = task & 3;                  // k-quarter: 8 heads
        int pair = tile * 256 + t;

        uint4 pk4 = g_packed[pair];           // one LDG.128: all 16 indices *4
        unsigned pk[4] = { pk4.x, pk4.y, pk4.z, pk4.w };
        float rden = __ldg(g_rden + pair);

        float acc[8];
#pragma unroll
        for (int j = 0; j < 8; ++j) acc[j] = 0.0f;

#pragma unroll
        for (int g = 0; g < 4; ++g) {         // d-group of 4: d = 4g..4g+3
            const char* base = (const char*)(shT + ((4 * g) * 16 + kq * 4) * 32);
            unsigned o0 =  pk[g]        & 0xFCu;
            unsigned o1 = (pk[g] >> 8)  & 0xFCu;
            unsigned o2 = (pk[g] >> 16) & 0xFCu;
            unsigned o3 = (pk[g] >> 24);
            const __half2* p0 = (const __half2*)(base          + o0);
            const __half2* p1 = (const __half2*)(base + 2048   + o1);
            const __half2* p2 = (const __half2*)(base + 4096   + o2);
            const __half2* p3 = (const __half2*)(base + 6144   + o3);
#pragma unroll
            for (int j = 0; j < 4; ++j) {     // 4 k2 slots in this quarter
                __half2 tt = __hadd2(__hadd2(p0[j * 32], p1[j * 32]),
                                     __hadd2(p2[j * 32], p3[j * 32]));
                float2 f = __half22float2(tt);
                acc[2 * j]     = fmaf(f.x, rden, acc[2 * j]);
                acc[2 * j + 1] = fmaf(f.y, rden, acc[2 * j + 1]);
            }
        }

        float* oe = out + (H + kq * 8) * PAIRS + pair;
#pragma unroll
        for (int j = 0; j < 8; ++j)
            oe[j * PAIRS] = acc[j];

        __syncthreads();       // publishes mail[slot]
        task = mail[slot];
        slot ^= 1;
    }
}

extern "C" void kernel_launch(void* const* d_in, const int* in_sizes, int n_in,
                              void* d_out, int out_size) {
    const int*   spatial_pos = nullptr;
    const int*   edge_input  = nullptr;
    const float* spd_table   = nullptr;
    const float* edge_table  = nullptr;
    const float* W           = nullptr;
    for (int i = 0; i < n_in; ++i) {
        switch (in_sizes[i]) {
            case PAIRS:          spatial_pos = (const int*)d_in[i];   break;
            case PAIRS * MAXD:   edge_input  = (const int*)d_in[i];   break;
            case NSPAT * H:      spd_table   = (const float*)d_in[i]; break;
            case H * H:          edge_table  = (const float*)d_in[i]; break;
            case NSPAT * H * H:  W           = (const float*)d_in[i]; break;
            default: break;
        }
    }

    // 16 T-blocks + 256 pack blocks (512 thr, 2 pairs/thread)
    prep_kernel<<<MAXD + PAIRS / 1024, 512>>>(edge_table, W, edge_input,
                                              spatial_pos, spd_table,
                                              (float*)d_out);

    cudaFuncSetAttribute(bond_encoding_kernel,
                         cudaFuncAttributeMaxDynamicSharedMemorySize, SMEM_BYTES);
    bond_encoding_kernel<<<GRID, 256, SMEM_BYTES>>>((float*)d_out);
}